// round 6
// baseline (speedup 1.0000x reference)
#include <cuda_runtime.h>
#include <cstdint>

// Problem constants (from reference)
#define F 8
#define B 4096
#define V 100000
#define D 128
#define NVALS 81920
#define CHUNK 32
#define CPF (NVALS / CHUNK)   // 2560 chunks per feature
#define STAGES 8              // per-warp smem pipeline depth (rows in flight)
#define WPB 8                 // warps per block

// Scratch: precomputed bag id for every jagged value (2.6 MB)
__device__ int g_seg[F * NVALS];

// Fused init: zero the output AND compute seg ids, one launch.
__global__ __launch_bounds__(256)
void init_kernel(const int* __restrict__ offsets,   // [F, B+1]
                 float4* __restrict__ out4)         // [B*F*D/4]
{
    const int id = blockIdx.x * blockDim.x + threadIdx.x;
    const int NT = F * NVALS;                       // 655,360

    // (a) zero output: 1,048,576 float4, grid-stride
    for (int i = id; i < (B * F * D) / 4; i += NT)
        out4[i] = make_float4(0.f, 0.f, 0.f, 0.f);

    // (b) seg[f][pos] = searchsorted(offs_f, pos, right) - 1
    const int f   = id / NVALS;
    const int pos = id - f * NVALS;
    const int* offs = offsets + f * (B + 1);
    int lo = 0, hi = B - 1;
    #pragma unroll
    for (int it = 0; it < 12; ++it) {
        int mid = (lo + hi + 1) >> 1;
        if (__ldg(offs + mid) <= pos) lo = mid; else hi = mid - 1;
    }
    g_seg[id] = lo;
}

template<int N>
__device__ __forceinline__ void cp_wait() {
    asm volatile("cp.async.wait_group %0;" :: "n"(N) : "memory");
}

// One warp per 32-value chunk (perfectly balanced). Row gathers staged through
// a per-warp 8-deep SMEM ring via cp.async: no destination registers held, so
// occupancy is no longer register-capped and in-flight bytes scale with warps.
// Each lane copies AND consumes its own 16B slice -> no __syncwarp needed.
__global__ __launch_bounds__(WPB * 32)
void ebc_chunk_kernel(const int* __restrict__ values,    // [F, NVALS]
                      const float* __restrict__ tables,  // [F, V, D]
                      float* __restrict__ out)           // [B, F*D]
{
    __shared__ float4 sbuf[WPB][STAGES][32];   // 32 KB

    const int wib   = threadIdx.x >> 5;
    const int lane  = threadIdx.x & 31;
    const int gwarp = blockIdx.x * WPB + wib;

    // f-major: consecutive warps share a table (L2 locality)
    const int f = gwarp / CPF;
    const int c = gwarp - f * CPF;
    const int pos = c * CHUNK + lane;          // this lane's value position

    const int myidx = __ldg(values + (size_t)f * NVALS + pos);
    const int myseg = __ldg(&g_seg[(size_t)f * NVALS + pos]);

    const float4* tab = reinterpret_cast<const float4*>(tables)
                        + (size_t)f * V * (D / 4) + lane;

    const uint32_t sbase =
        (uint32_t)__cvta_generic_to_shared(&sbuf[wib][0][lane]);

    // issue row r's 512B gather into stage r % STAGES (one 16B cp.async/lane)
    auto issue = [&](int r) {
        const int row = __shfl_sync(0xffffffffu, myidx, r);
        const float4* src = tab + (size_t)row * (D / 4);
        const uint32_t dst = sbase + (uint32_t)((r & (STAGES - 1)) * 32) * 16u;
        asm volatile("cp.async.cg.shared.global [%0], [%1], 16;\n\t"
                     "cp.async.commit_group;"
                     :: "r"(dst), "l"(src) : "memory");
    };

    // prologue: fill the ring
    #pragma unroll
    for (int r = 0; r < STAGES; ++r) issue(r);

    float4 acc = make_float4(0.f, 0.f, 0.f, 0.f);
    int cur = __shfl_sync(0xffffffffu, myseg, 0);

    auto consume = [&](int j) {
        const float4 v = sbuf[wib][j & (STAGES - 1)][lane];
        const int s = __shfl_sync(0xffffffffu, myseg, j);
        if (s != cur) {                        // warp-uniform branch
            float* o = out + (size_t)cur * (F * D) + f * D + lane * 4;
            asm volatile("red.global.add.v4.f32 [%0], {%1,%2,%3,%4};"
                         :: "l"(o), "f"(acc.x), "f"(acc.y), "f"(acc.z), "f"(acc.w)
                         : "memory");
            acc = make_float4(0.f, 0.f, 0.f, 0.f);
            cur = s;
        }
        acc.x += v.x; acc.y += v.y; acc.z += v.z; acc.w += v.w;
    };

    // steady state: wait oldest, consume, refill
    #pragma unroll
    for (int j = 0; j < CHUNK - STAGES; ++j) {
        cp_wait<STAGES - 1>();
        consume(j);
        issue(j + STAGES);
    }
    // tail: everything issued; drain
    cp_wait<0>();
    #pragma unroll
    for (int j = CHUNK - STAGES; j < CHUNK; ++j) consume(j);

    // final flush
    float* o = out + (size_t)cur * (F * D) + f * D + lane * 4;
    asm volatile("red.global.add.v4.f32 [%0], {%1,%2,%3,%4};"
                 :: "l"(o), "f"(acc.x), "f"(acc.y), "f"(acc.z), "f"(acc.w)
                 : "memory");
}

extern "C" void kernel_launch(void* const* d_in, const int* in_sizes, int n_in,
                              void* d_out, int out_size)
{
    const int*   values  = (const int*)d_in[0];   // [F, NVALS] int32
    const int*   offsets = (const int*)d_in[1];   // [F, B+1] int32
    const float* tables  = (const float*)d_in[2]; // [F, V, D] float32
    float*       out     = (float*)d_out;         // [B, F*D] float32

    // 1) fused zero-output + seg precompute
    init_kernel<<<(F * NVALS) / 256, 256>>>(offsets, (float4*)out);

    // 2) balanced, smem-pipelined gather + segment-reduce
    const int total_warps = F * CPF;               // 20480
    const int blocks = total_warps / WPB;          // 2560
    ebc_chunk_kernel<<<blocks, WPB * 32>>>(values, tables, out);
}

// round 7
// speedup vs baseline: 1.0750x; 1.0750x over previous
#include <cuda_runtime.h>
#include <cstdint>

// Problem constants (from reference)
#define F 8
#define B 4096
#define V 100000
#define D 128
#define NVALS 81920
#define CHUNK 32
#define CPF (NVALS / CHUNK)   // 2560 chunks per feature
#define STAGES 8              // per-warp smem pipeline depth (rows in flight)
#define WPB 8                 // warps per block

template<int N>
__device__ __forceinline__ void cp_wait() {
    asm volatile("cp.async.wait_group %0;" :: "n"(N) : "memory");
}

// One warp per 32-value chunk (perfectly balanced). Row gathers staged through
// a per-warp 8-deep SMEM ring via cp.async. Bag ids are found by an inline
// per-lane binary search that executes WHILE the prologue gathers are in
// flight, so its latency is fully hidden. Partial bag sums flushed with one
// red.global.add.v4.f32 per lane (output pre-zeroed by a memset node).
__global__ __launch_bounds__(WPB * 32)
void ebc_chunk_kernel(const int* __restrict__ values,    // [F, NVALS]
                      const int* __restrict__ offsets,   // [F, B+1]
                      const float* __restrict__ tables,  // [F, V, D]
                      float* __restrict__ out)           // [B, F*D]
{
    __shared__ float4 sbuf[WPB][STAGES][32];   // 32 KB

    const int wib   = threadIdx.x >> 5;
    const int lane  = threadIdx.x & 31;
    const int gwarp = blockIdx.x * WPB + wib;

    // f-major: consecutive warps share a table (L2 locality)
    const int f = gwarp / CPF;
    const int c = gwarp - f * CPF;
    const int pos = c * CHUNK + lane;          // this lane's value position

    const int myidx = __ldg(values + (size_t)f * NVALS + pos);

    const float4* tab = reinterpret_cast<const float4*>(tables)
                        + (size_t)f * V * (D / 4) + lane;

    const uint32_t sbase =
        (uint32_t)__cvta_generic_to_shared(&sbuf[wib][0][lane]);

    // issue row r's 512B gather into stage r % STAGES (one 16B cp.async/lane)
    auto issue = [&](int r) {
        const int row = __shfl_sync(0xffffffffu, myidx, r);
        const float4* src = tab + (size_t)row * (D / 4);
        const uint32_t dst = sbase + (uint32_t)((r & (STAGES - 1)) * 32) * 16u;
        asm volatile("cp.async.cg.shared.global [%0], [%1], 16;\n\t"
                     "cp.async.commit_group;"
                     :: "r"(dst), "l"(src) : "memory");
    };

    // prologue: fill the ring FIRST -> DRAM latency covers the search below
    #pragma unroll
    for (int r = 0; r < STAGES; ++r) issue(r);

    // bag id = largest j in [0, B-1] with offs[j] <= pos (searchsorted right - 1)
    // 12 dependent L1 loads, hidden under the in-flight gathers above.
    const int* offs = offsets + f * (B + 1);
    int lo = 0, hi = B - 1;
    #pragma unroll
    for (int it = 0; it < 12; ++it) {          // 2^12 = 4096 covers [0, B-1]
        int mid = (lo + hi + 1) >> 1;
        if (__ldg(offs + mid) <= pos) lo = mid; else hi = mid - 1;
    }
    const int myseg = lo;

    float4 acc = make_float4(0.f, 0.f, 0.f, 0.f);
    int cur = __shfl_sync(0xffffffffu, myseg, 0);

    auto consume = [&](int j) {
        const float4 v = sbuf[wib][j & (STAGES - 1)][lane];
        const int s = __shfl_sync(0xffffffffu, myseg, j);
        if (s != cur) {                        // warp-uniform branch
            float* o = out + (size_t)cur * (F * D) + f * D + lane * 4;
            asm volatile("red.global.add.v4.f32 [%0], {%1,%2,%3,%4};"
                         :: "l"(o), "f"(acc.x), "f"(acc.y), "f"(acc.z), "f"(acc.w)
                         : "memory");
            acc = make_float4(0.f, 0.f, 0.f, 0.f);
            cur = s;
        }
        acc.x += v.x; acc.y += v.y; acc.z += v.z; acc.w += v.w;
    };

    // steady state: wait oldest, consume, refill
    #pragma unroll
    for (int j = 0; j < CHUNK - STAGES; ++j) {
        cp_wait<STAGES - 1>();
        consume(j);
        issue(j + STAGES);
    }
    // tail: everything issued; drain
    cp_wait<0>();
    #pragma unroll
    for (int j = CHUNK - STAGES; j < CHUNK; ++j) consume(j);

    // final flush
    float* o = out + (size_t)cur * (F * D) + f * D + lane * 4;
    asm volatile("red.global.add.v4.f32 [%0], {%1,%2,%3,%4};"
                 :: "l"(o), "f"(acc.x), "f"(acc.y), "f"(acc.z), "f"(acc.w)
                 : "memory");
}

extern "C" void kernel_launch(void* const* d_in, const int* in_sizes, int n_in,
                              void* d_out, int out_size)
{
    const int*   values  = (const int*)d_in[0];   // [F, NVALS] int32
    const int*   offsets = (const int*)d_in[1];   // [F, B+1] int32
    const float* tables  = (const float*)d_in[2]; // [F, V, D] float32
    float*       out     = (float*)d_out;         // [B, F*D] float32

    // 1) zero the output with a graph memset node (atomics accumulate into it)
    cudaMemsetAsync(out, 0, (size_t)B * F * D * sizeof(float), 0);

    // 2) balanced, smem-pipelined gather + segment-reduce (seg inline)
    const int total_warps = F * CPF;               // 20480
    const int blocks = total_warps / WPB;          // 2560
    ebc_chunk_kernel<<<blocks, WPB * 32>>>(values, offsets, tables, out);
}

// round 9
// speedup vs baseline: 1.1115x; 1.0339x over previous
#include <cuda_runtime.h>
#include <cstdint>

// Problem constants (from reference)
#define F 8
#define B 4096
#define V 100000
#define D 128
#define NVALS 81920
#define CHUNK 32
#define CPF (NVALS / CHUNK)   // 2560 chunks per feature (divisible by WPB)
#define STAGES 8              // per-warp smem pipeline depth (rows in flight)
#define WPB 8                 // warps per block
#define TPB (WPB * 32)        // 256 threads: block covers 256 consecutive positions

template<int N>
__device__ __forceinline__ void cp_wait() {
    asm volatile("cp.async.wait_group %0;" :: "n"(N) : "memory");
}

// One warp per 32-value chunk (perfectly balanced). Row gathers staged through
// a per-warp 8-deep SMEM ring via cp.async. Bag ids computed block-
// cooperatively: one uniform bsearch + one coalesced boundary load into smem
// + per-thread smem upper_bound (9 iters over 257-value range, INT_MAX
// sentinel makes converged iterations stable no-ops). Partial bag sums
// flushed with red.global.add.v4.f32 (output pre-zeroed by a memset node).
__global__ __launch_bounds__(TPB)
void ebc_chunk_kernel(const int* __restrict__ values,    // [F, NVALS]
                      const int* __restrict__ offsets,   // [F, B+1]
                      const float* __restrict__ tables,  // [F, V, D]
                      float* __restrict__ out)           // [B, F*D]
{
    __shared__ float4 sbuf[WPB][STAGES][32];   // 32 KB gather ring
    __shared__ int sb[TPB + 1];                // boundaries offs[s0+1..s0+256] + sentinel
    __shared__ int s_s0;

    const int wib   = threadIdx.x >> 5;
    const int lane  = threadIdx.x & 31;
    const int gwarp = blockIdx.x * WPB + wib;

    // f-major: all warps of a block share one feature/table (L2 locality)
    const int f = gwarp / CPF;
    const int c = gwarp - f * CPF;
    const int pos = c * CHUNK + lane;          // this lane's value position

    const int myidx = __ldg(values + (size_t)f * NVALS + pos);

    const float4* tab = reinterpret_cast<const float4*>(tables)
                        + (size_t)f * V * (D / 4) + lane;

    const uint32_t sbase =
        (uint32_t)__cvta_generic_to_shared(&sbuf[wib][0][lane]);

    // issue row r's 512B gather into stage r % STAGES (one 16B cp.async/lane)
    auto issue = [&](int r) {
        const int row = __shfl_sync(0xffffffffu, myidx, r);
        const float4* src = tab + (size_t)row * (D / 4);
        const uint32_t dst = sbase + (uint32_t)((r & (STAGES - 1)) * 32) * 16u;
        asm volatile("cp.async.cg.shared.global [%0], [%1], 16;\n\t"
                     "cp.async.commit_group;"
                     :: "r"(dst), "l"(src) : "memory");
    };

    // prologue: fill the ring FIRST, then do the segment lookup under it
    #pragma unroll
    for (int r = 0; r < STAGES; ++r) issue(r);

    // ---- block-cooperative segment lookup ----
    const int* offs = offsets + f * (B + 1);
    const int P0 = ((blockIdx.x * WPB) - f * CPF) * CHUNK;  // block's first position

    if (wib == 0) {
        // uniform bsearch for seg(P0): every lane same address -> broadcast
        int lo = 0, hi = B - 1;
        #pragma unroll
        for (int it = 0; it < 12; ++it) {      // 2^12 = 4096 covers [0, B-1]
            int mid = (lo + hi + 1) >> 1;
            if (__ldg(offs + mid) <= P0) lo = mid; else hi = mid - 1;
        }
        if (lane == 0) s_s0 = lo;
    }
    __syncthreads();
    const int s0 = s_s0;

    // coalesced load of the next 256 boundaries (clamped; offs[B]=N > any pos)
    {
        int j = s0 + 1 + threadIdx.x;
        sb[threadIdx.x] = __ldg(offs + (j > B ? B : j));
    }
    if (threadIdx.x == 0) sb[TPB] = 0x7fffffff;   // sentinel
    __syncthreads();

    // cnt = upper_bound(sb[0..255], pos): first index with sb[idx] > pos.
    // Range of answers is [0,256] (257 values) -> 9 iterations; the sentinel
    // at sb[256] makes post-convergence iterations stable.
    int cnt;
    {
        int lo = 0, hi = TPB;
        #pragma unroll
        for (int it = 0; it < 9; ++it) {
            int mid = (lo + hi) >> 1;
            if (sb[mid] <= pos) lo = mid + 1; else hi = mid;
        }
        cnt = lo;
    }
    int myseg = s0 + cnt;
    if (cnt == TPB) {
        // pathological window (>=256 bags in 256 positions): exact global bsearch
        int lo = 0, hi = B - 1;
        for (int it = 0; it < 12; ++it) {
            int mid = (lo + hi + 1) >> 1;
            if (__ldg(offs + mid) <= pos) lo = mid; else hi = mid - 1;
        }
        myseg = lo;
    }
    // ---- end segment lookup ----

    float4 acc = make_float4(0.f, 0.f, 0.f, 0.f);
    int cur = __shfl_sync(0xffffffffu, myseg, 0);

    auto consume = [&](int j) {
        const float4 v = sbuf[wib][j & (STAGES - 1)][lane];
        const int s = __shfl_sync(0xffffffffu, myseg, j);
        if (s != cur) {                        // warp-uniform branch
            float* o = out + (size_t)cur * (F * D) + f * D + lane * 4;
            asm volatile("red.global.add.v4.f32 [%0], {%1,%2,%3,%4};"
                         :: "l"(o), "f"(acc.x), "f"(acc.y), "f"(acc.z), "f"(acc.w)
                         : "memory");
            acc = make_float4(0.f, 0.f, 0.f, 0.f);
            cur = s;
        }
        acc.x += v.x; acc.y += v.y; acc.z += v.z; acc.w += v.w;
    };

    // steady state: wait oldest, consume, refill
    #pragma unroll
    for (int j = 0; j < CHUNK - STAGES; ++j) {
        cp_wait<STAGES - 1>();
        consume(j);
        issue(j + STAGES);
    }
    // tail: everything issued; drain
    cp_wait<0>();
    #pragma unroll
    for (int j = CHUNK - STAGES; j < CHUNK; ++j) consume(j);

    // final flush
    float* o = out + (size_t)cur * (F * D) + f * D + lane * 4;
    asm volatile("red.global.add.v4.f32 [%0], {%1,%2,%3,%4};"
                 :: "l"(o), "f"(acc.x), "f"(acc.y), "f"(acc.z), "f"(acc.w)
                 : "memory");
}

extern "C" void kernel_launch(void* const* d_in, const int* in_sizes, int n_in,
                              void* d_out, int out_size)
{
    const int*   values  = (const int*)d_in[0];   // [F, NVALS] int32
    const int*   offsets = (const int*)d_in[1];   // [F, B+1] int32
    const float* tables  = (const float*)d_in[2]; // [F, V, D] float32
    float*       out     = (float*)d_out;         // [B, F*D] float32

    // 1) zero the output with a graph memset node (atomics accumulate into it)
    cudaMemsetAsync(out, 0, (size_t)B * F * D * sizeof(float), 0);

    // 2) balanced, smem-pipelined gather + segment-reduce
    const int total_warps = F * CPF;               // 20480
    const int blocks = total_warps / WPB;          // 2560
    ebc_chunk_kernel<<<blocks, TPB>>>(values, offsets, tables, out);
}